// round 10
// baseline (speedup 1.0000x reference)
#include <cuda_runtime.h>
#include <stdint.h>

// Problem constants (reference: D=256, H=256, P=524288)
#define THREADS   512
#define M_TILE    128
#define SA_STRIDE 68    // layer-1 A chunk stride (mod 32 == 4 -> conflict-free frags)
#define SX_STRIDE 260   // activation buffer stride (mod 32 == 4)
#define SW_STRIDE 264   // weight chunk stride (mod 32 == 8 -> conflict-free B frags)

static const int SX_FLOATS = M_TILE * SX_STRIDE;   // 33280
static const int SW_FLOATS = 64 * SW_STRIDE;       // 16896
static const size_t SMEM_BYTES = (size_t)(SX_FLOATS + SW_FLOATS) * 4 + 256 * 4; // ~201.7 KB

// round fp32 -> tf32 (round-to-nearest) keeping fp32 bit container
__device__ __forceinline__ float tf32r(float x) {
    uint32_t u;
    asm("cvt.rna.tf32.f32 %0, %1;" : "=r"(u) : "f"(x));
    return __uint_as_float(u);
}

__device__ __forceinline__ void mma_tf32(float (&d)[4], const uint32_t (&a)[4],
                                         uint32_t b0, uint32_t b1) {
    asm volatile(
        "mma.sync.aligned.m16n8k8.row.col.f32.tf32.tf32.f32 "
        "{%0,%1,%2,%3},{%4,%5,%6,%7},{%8,%9},{%0,%1,%2,%3};\n"
        : "+f"(d[0]), "+f"(d[1]), "+f"(d[2]), "+f"(d[3])
        : "r"(a[0]), "r"(a[1]), "r"(a[2]), "r"(a[3]), "r"(b0), "r"(b1));
}

__global__ void __launch_bounds__(THREADS, 1)
edge_mlp_kernel(const float* __restrict__ h_nodes,
                const int*   __restrict__ dst,
                const int*   __restrict__ src,
                const float* __restrict__ W1,
                const float* __restrict__ W2,
                const float* __restrict__ W3,
                float*       __restrict__ out,
                int P)
{
    extern __shared__ float smem[];
    float* sX   = smem;                       // [128][260] activations (x1 tf32, then x2 fp32)
    float* sW   = smem + SX_FLOATS;           // [64][264] weight k-chunk
    int*   sIdx = (int*)(smem + SX_FLOATS + SW_FLOATS); // [256] dst|src node ids

    const int tid  = threadIdx.x;
    const int lane = tid & 31;
    const int wid  = tid >> 5;
    const int wm   = wid >> 2;   // warp row 0..3 (32 rows each)
    const int wn   = wid & 3;    // warp col 0..3 (64 cols each)
    const int g    = lane >> 2;  // groupID 0..7
    const int t    = lane & 3;   // threadID-in-group 0..3

    const int tile0 = blockIdx.x * M_TILE;

    if (tid < M_TILE) {
        int p = tile0 + tid; if (p >= P) p = P - 1;
        sIdx[tid]          = dst[p];
        sIdx[M_TILE + tid] = src[p];
    }

    float acc[2][8][4];
#pragma unroll
    for (int i = 0; i < 2; i++)
#pragma unroll
        for (int j = 0; j < 8; j++)
#pragma unroll
            for (int c = 0; c < 4; c++) acc[i][j][c] = 0.f;

    // ================= Layer 1: [128,512] @ W1[512,256], K in 8 chunks =================
    for (int kc = 0; kc < 8; kc++) {
        __syncthreads();  // (covers sIdx stores on first iter, sX/sW reuse otherwise)

        // Gather A chunk [128][64]: cols [kc*64, kc*64+64) of concat(h[dst], h[src])
#pragma unroll
        for (int q = 0; q < 4; q++) {
            int idx = tid + q * THREADS;   // 0..2047
            int r   = idx >> 4;            // row 0..127
            int c4  = idx & 15;            // float4 index 0..15
            int node = sIdx[r + ((kc >= 4) ? M_TILE : 0)];
            const float4 v = *(const float4*)(h_nodes + (size_t)node * 256
                                              + ((kc & 3) << 6) + (c4 << 2));
            float* dp = sX + r * SA_STRIDE + (c4 << 2);
            dp[0] = tf32r(v.x); dp[1] = tf32r(v.y); dp[2] = tf32r(v.z); dp[3] = tf32r(v.w);
        }
        // W1 chunk: rows [kc*64, kc*64+64), all 256 cols
#pragma unroll
        for (int q = 0; q < 8; q++) {
            int idx = tid + q * THREADS;   // 0..4095
            int kr  = idx >> 6;            // 0..63
            int c4  = idx & 63;            // 0..63
            const float4 v = *(const float4*)(W1 + ((size_t)(kc * 64 + kr)) * 256 + (c4 << 2));
            float* dp = sW + kr * SW_STRIDE + (c4 << 2);
            dp[0] = tf32r(v.x); dp[1] = tf32r(v.y); dp[2] = tf32r(v.z); dp[3] = tf32r(v.w);
        }
        __syncthreads();

#pragma unroll
        for (int ks = 0; ks < 8; ks++) {
            const int k0 = ks << 3;
            uint32_t a[2][4];
#pragma unroll
            for (int i = 0; i < 2; i++) {
                const int rb = wm * 32 + i * 16;
                a[i][0] = __float_as_uint(sX[(rb + g)     * SA_STRIDE + k0     + t]);
                a[i][1] = __float_as_uint(sX[(rb + 8 + g) * SA_STRIDE + k0     + t]);
                a[i][2] = __float_as_uint(sX[(rb + g)     * SA_STRIDE + k0 + 4 + t]);
                a[i][3] = __float_as_uint(sX[(rb + 8 + g) * SA_STRIDE + k0 + 4 + t]);
            }
#pragma unroll
            for (int j = 0; j < 8; j++) {
                const int cb = wn * 64 + j * 8;
                uint32_t b0 = __float_as_uint(sW[(k0 + t)     * SW_STRIDE + cb + g]);
                uint32_t b1 = __float_as_uint(sW[(k0 + 4 + t) * SW_STRIDE + cb + g]);
                mma_tf32(acc[0][j], a[0], b0, b1);
                mma_tf32(acc[1][j], a[1], b0, b1);
            }
        }
    }
    __syncthreads();  // all mma reads of sX/sW done

    // relu + tf32-round -> store x1 into sX [128][260]; reset accumulators
#pragma unroll
    for (int i = 0; i < 2; i++) {
        const int rb = wm * 32 + i * 16;
#pragma unroll
        for (int j = 0; j < 8; j++) {
            const int cb = wn * 64 + j * 8 + 2 * t;
            sX[(rb + g)     * SX_STRIDE + cb]     = tf32r(fmaxf(acc[i][j][0], 0.f));
            sX[(rb + g)     * SX_STRIDE + cb + 1] = tf32r(fmaxf(acc[i][j][1], 0.f));
            sX[(rb + 8 + g) * SX_STRIDE + cb]     = tf32r(fmaxf(acc[i][j][2], 0.f));
            sX[(rb + 8 + g) * SX_STRIDE + cb + 1] = tf32r(fmaxf(acc[i][j][3], 0.f));
            acc[i][j][0] = 0.f; acc[i][j][1] = 0.f; acc[i][j][2] = 0.f; acc[i][j][3] = 0.f;
        }
    }

    // ================= Layer 2: x1[128,256] @ W2[256,256], K in 4 chunks =================
    for (int kc = 0; kc < 4; kc++) {
        __syncthreads();  // x1 stores visible / previous sW reads done
#pragma unroll
        for (int q = 0; q < 8; q++) {
            int idx = tid + q * THREADS;
            int kr  = idx >> 6;
            int c4  = idx & 63;
            const float4 v = *(const float4*)(W2 + ((size_t)(kc * 64 + kr)) * 256 + (c4 << 2));
            float* dp = sW + kr * SW_STRIDE + (c4 << 2);
            dp[0] = tf32r(v.x); dp[1] = tf32r(v.y); dp[2] = tf32r(v.z); dp[3] = tf32r(v.w);
        }
        __syncthreads();

#pragma unroll
        for (int ks = 0; ks < 8; ks++) {
            const int kW = ks << 3;            // k within the smem weight chunk
            const int kA = kc * 64 + kW;       // k within resident x1
            uint32_t a[2][4];
#pragma unroll
            for (int i = 0; i < 2; i++) {
                const int rb = wm * 32 + i * 16;
                a[i][0] = __float_as_uint(sX[(rb + g)     * SX_STRIDE + kA     + t]);
                a[i][1] = __float_as_uint(sX[(rb + 8 + g) * SX_STRIDE + kA     + t]);
                a[i][2] = __float_as_uint(sX[(rb + g)     * SX_STRIDE + kA + 4 + t]);
                a[i][3] = __float_as_uint(sX[(rb + 8 + g) * SX_STRIDE + kA + 4 + t]);
            }
#pragma unroll
            for (int j = 0; j < 8; j++) {
                const int cb = wn * 64 + j * 8;
                uint32_t b0 = __float_as_uint(sW[(kW + t)     * SW_STRIDE + cb + g]);
                uint32_t b1 = __float_as_uint(sW[(kW + 4 + t) * SW_STRIDE + cb + g]);
                mma_tf32(acc[0][j], a[0], b0, b1);
                mma_tf32(acc[1][j], a[1], b0, b1);
            }
        }
    }
    __syncthreads();  // all mma reads of sX (x1) / sW done

    // relu -> store x2 (full fp32) into sX; stage W3 into sW
#pragma unroll
    for (int i = 0; i < 2; i++) {
        const int rb = wm * 32 + i * 16;
#pragma unroll
        for (int j = 0; j < 8; j++) {
            const int cb = wn * 64 + j * 8 + 2 * t;
            sX[(rb + g)     * SX_STRIDE + cb]     = fmaxf(acc[i][j][0], 0.f);
            sX[(rb + g)     * SX_STRIDE + cb + 1] = fmaxf(acc[i][j][1], 0.f);
            sX[(rb + 8 + g) * SX_STRIDE + cb]     = fmaxf(acc[i][j][2], 0.f);
            sX[(rb + 8 + g) * SX_STRIDE + cb + 1] = fmaxf(acc[i][j][3], 0.f);
        }
    }
    if (tid < 256) {                 // W3 is [256,2] = 512 floats
        sW[tid]       = W3[tid];
        sW[256 + tid] = W3[256 + tid];
    }
    __syncthreads();

    // ================= Layer 3: out[p, o] = x2[r,:] . W3[:, o] (exact fp32) =============
    if (tid < 256) {
        const int r = tid >> 1;
        const int o = tid & 1;
        const int p = tile0 + r;
        if (p < P) {
            const float* xr = sX + r * SX_STRIDE;
            float s = 0.f;
#pragma unroll 8
            for (int k = 0; k < 256; k++)
                s = fmaf(xr[k], sW[k * 2 + o], s);
            out[(size_t)p * 2 + o] = s;
        }
    }
}

extern "C" void kernel_launch(void* const* d_in, const int* in_sizes, int n_in,
                              void* d_out, int out_size)
{
    const float* h_nodes = (const float*)d_in[0];
    const int*   dst     = (const int*)  d_in[1];
    const int*   src     = (const int*)  d_in[2];
    const float* W1      = (const float*)d_in[3];
    const float* W2      = (const float*)d_in[4];
    const float* W3      = (const float*)d_in[5];
    float*       out     = (float*)d_out;

    const int P = in_sizes[1];   // number of pairs (dst element count)

    cudaFuncSetAttribute(edge_mlp_kernel,
                         cudaFuncAttributeMaxDynamicSharedMemorySize,
                         (int)SMEM_BYTES);

    const int grid = (P + M_TILE - 1) / M_TILE;
    edge_mlp_kernel<<<grid, THREADS, SMEM_BYTES>>>(h_nodes, dst, src, W1, W2, W3, out, P);
}

// round 11
// speedup vs baseline: 1.0807x; 1.0807x over previous
#include <cuda_runtime.h>
#include <stdint.h>

// Problem constants (reference: D=256, H=256, P=524288)
#define THREADS   512
#define M_TILE    128
#define KC        32            // K chunk (pipeline stage granularity)
#define SA_STRIDE 36            // A chunk row stride (mod 32 == 4 -> conflict-free frags)
#define SX_STRIDE 260           // activation buffer stride (mod 32 == 4)
#define SW_STRIDE 264           // weight chunk stride (mod 32 == 8 -> conflict-free B frags)

#define SA_BUF_FLOATS (M_TILE * SA_STRIDE)     // 4608 (x2 buffers overlaid in sX)
#define SX_FLOATS     (M_TILE * SX_STRIDE)     // 33280
#define SW_BUF_FLOATS (KC * SW_STRIDE)         // 8448
#define SMEM_FLOATS   (SX_FLOATS + 2 * SW_BUF_FLOATS)   // 50176 -> 196 KB

// fp32 -> tf32 (round-to-nearest) as mma-ready uint32
__device__ __forceinline__ uint32_t f2tf(float x) {
    uint32_t u;
    asm("cvt.rna.tf32.f32 %0, %1;" : "=r"(u) : "f"(x));
    return u;
}
__device__ __forceinline__ float tf32r(float x) {
    uint32_t u;
    asm("cvt.rna.tf32.f32 %0, %1;" : "=r"(u) : "f"(x));
    return __uint_as_float(u);
}

__device__ __forceinline__ void mma_tf32(float (&d)[4], const uint32_t (&a)[4],
                                         uint32_t b0, uint32_t b1) {
    asm volatile(
        "mma.sync.aligned.m16n8k8.row.col.f32.tf32.tf32.f32 "
        "{%0,%1,%2,%3},{%4,%5,%6,%7},{%8,%9},{%0,%1,%2,%3};\n"
        : "+f"(d[0]), "+f"(d[1]), "+f"(d[2]), "+f"(d[3])
        : "r"(a[0]), "r"(a[1]), "r"(a[2]), "r"(a[3]), "r"(b0), "r"(b1));
}

__device__ __forceinline__ void cp16(void* sdst, const void* gsrc) {
    uint32_t s = (uint32_t)__cvta_generic_to_shared(sdst);
    asm volatile("cp.async.cg.shared.global [%0], [%1], 16;\n" :: "r"(s), "l"(gsrc));
}
__device__ __forceinline__ void cp_commit() {
    asm volatile("cp.async.commit_group;\n");
}
template <int N>
__device__ __forceinline__ void cp_wait() {
    asm volatile("cp.async.wait_group %0;\n" :: "n"(N));
}

// One K=32 chunk of mmas: A [128, KC] (raw fp32, stride aStride), B [KC, 256] (raw fp32)
__device__ __forceinline__ void compute_chunk(const float* __restrict__ sA, int aStride,
                                              const float* __restrict__ sWb,
                                              float (&acc)[2][8][4],
                                              int wm, int wn, int g, int t)
{
#pragma unroll
    for (int ks = 0; ks < 4; ks++) {
        const int k0 = ks << 3;
        uint32_t a[2][4];
#pragma unroll
        for (int i = 0; i < 2; i++) {
            const int rb = wm * 32 + i * 16;
            a[i][0] = f2tf(sA[(rb + g)     * aStride + k0     + t]);
            a[i][1] = f2tf(sA[(rb + 8 + g) * aStride + k0     + t]);
            a[i][2] = f2tf(sA[(rb + g)     * aStride + k0 + 4 + t]);
            a[i][3] = f2tf(sA[(rb + 8 + g) * aStride + k0 + 4 + t]);
        }
#pragma unroll
        for (int j = 0; j < 8; j++) {
            const int cb = wn * 64 + j * 8;
            uint32_t b0 = f2tf(sWb[(k0 + t)     * SW_STRIDE + cb + g]);
            uint32_t b1 = f2tf(sWb[(k0 + 4 + t) * SW_STRIDE + cb + g]);
            mma_tf32(acc[0][j], a[0], b0, b1);
            mma_tf32(acc[1][j], a[1], b0, b1);
        }
    }
}

__global__ void __launch_bounds__(THREADS, 1)
edge_mlp_kernel(const float* __restrict__ h_nodes,
                const int*   __restrict__ dst,
                const int*   __restrict__ src,
                const float* __restrict__ W1,
                const float* __restrict__ W2,
                const float* __restrict__ W3,
                float*       __restrict__ out,
                int P)
{
    extern __shared__ float smem[];
    float* sX = smem;                 // [128][260] activations; sA double-buffer overlaid at [0, 9216)
    float* sW = smem + SX_FLOATS;     // 2 x [32][264] weight chunk buffers

    const int tid  = threadIdx.x;
    const int lane = tid & 31;
    const int wid  = tid >> 5;
    const int wm   = wid >> 2;        // warp row 0..3 (32 rows each)
    const int wn   = wid & 3;         // warp col 0..3 (64 cols each)
    const int g    = lane >> 2;       // groupID 0..7
    const int t    = lane & 3;        // threadID-in-group 0..3

    const int tile0 = blockIdx.x * M_TILE;

    // Per-thread A-staging slots: rows r0 = tid>>3 and r1 = r0+64, float4 col c4 = tid&7
    const int r0 = tid >> 3;
    const int r1 = r0 + 64;
    const int c4 = tid & 7;
    int p0 = tile0 + r0; if (p0 >= P) p0 = P - 1;
    int p1 = tile0 + r1; if (p1 >= P) p1 = P - 1;
    const size_t nd0 = (size_t)dst[p0] * 256, nd1 = (size_t)dst[p1] * 256;
    const size_t ns0 = (size_t)src[p0] * 256, ns1 = (size_t)src[p1] * 256;

    // ---- stage-issue helpers (inlined logic) ----
    // A chunk kc (0..15): cols [kc*32, kc*32+32) of concat(h[dst], h[src])
    auto issue_A = [&](int kc, float* sAbuf) {
        const int colb = ((kc & 7) << 5) + (c4 << 2);
        const size_t n0 = (kc < 8) ? nd0 : ns0;
        const size_t n1 = (kc < 8) ? nd1 : ns1;
        cp16(sAbuf + r0 * SA_STRIDE + (c4 << 2), h_nodes + n0 + colb);
        cp16(sAbuf + r1 * SA_STRIDE + (c4 << 2), h_nodes + n1 + colb);
    };
    // W chunk kc: rows [kc*32, kc*32+32), 256 cols
    auto issue_W = [&](const float* W, int kc, float* sWbuf) {
#pragma unroll
        for (int q = 0; q < 4; q++) {
            int idx = tid + q * THREADS;          // 0..2047
            int kr  = idx >> 6;                   // 0..31
            int cw  = idx & 63;                   // float4 col 0..63
            cp16(sWbuf + kr * SW_STRIDE + (cw << 2),
                 W + ((size_t)(kc * KC + kr)) * 256 + (cw << 2));
        }
    };

    float acc[2][8][4];
#pragma unroll
    for (int i = 0; i < 2; i++)
#pragma unroll
        for (int j = 0; j < 8; j++)
#pragma unroll
            for (int c = 0; c < 4; c++) acc[i][j][c] = 0.f;

    // ================= Layer 1: [128,512] @ W1[512,256], 16 pipelined chunks ==========
    issue_A(0, sX);
    issue_W(W1, 0, sW);
    cp_commit();

    for (int kc = 0; kc < 16; kc++) {
        if (kc < 15) {
            issue_A(kc + 1, sX + ((kc + 1) & 1) * SA_BUF_FLOATS);
            issue_W(W1, kc + 1, sW + ((kc + 1) & 1) * SW_BUF_FLOATS);
        } else {
            issue_W(W2, 0, sW);   // prefetch layer-2 chunk 0 (keeps group cadence)
        }
        cp_commit();
        cp_wait<1>();
        __syncthreads();
        compute_chunk(sX + (kc & 1) * SA_BUF_FLOATS, SA_STRIDE,
                      sW + (kc & 1) * SW_BUF_FLOATS, acc, wm, wn, g, t);
        __syncthreads();
    }

    // relu + tf32-round -> x1 into sX [128][260] (sA overlay now dead); reset acc.
    // L2 W2 chunk-0 cp.async overlaps this epilogue.
#pragma unroll
    for (int i = 0; i < 2; i++) {
        const int rb = wm * 32 + i * 16;
#pragma unroll
        for (int j = 0; j < 8; j++) {
            const int cb = wn * 64 + j * 8 + 2 * t;
            sX[(rb + g)     * SX_STRIDE + cb]     = tf32r(fmaxf(acc[i][j][0], 0.f));
            sX[(rb + g)     * SX_STRIDE + cb + 1] = tf32r(fmaxf(acc[i][j][1], 0.f));
            sX[(rb + 8 + g) * SX_STRIDE + cb]     = tf32r(fmaxf(acc[i][j][2], 0.f));
            sX[(rb + 8 + g) * SX_STRIDE + cb + 1] = tf32r(fmaxf(acc[i][j][3], 0.f));
            acc[i][j][0] = 0.f; acc[i][j][1] = 0.f; acc[i][j][2] = 0.f; acc[i][j][3] = 0.f;
        }
    }

    // ================= Layer 2: x1[128,256] @ W2[256,256], 8 pipelined chunks =========
    for (int kc = 0; kc < 8; kc++) {
        if (kc < 7) {
            issue_W(W2, kc + 1, sW + ((kc + 1) & 1) * SW_BUF_FLOATS);
            cp_commit();
            cp_wait<1>();
        } else {
            cp_wait<0>();
        }
        __syncthreads();   // chunk kc ready; also makes x1 stores visible on kc==0
        compute_chunk(sX + kc * KC, SX_STRIDE,
                      sW + (kc & 1) * SW_BUF_FLOATS, acc, wm, wn, g, t);
        __syncthreads();
    }

    // relu -> x2 (full fp32) into sX; stage W3 into sW (free now)
#pragma unroll
    for (int i = 0; i < 2; i++) {
        const int rb = wm * 32 + i * 16;
#pragma unroll
        for (int j = 0; j < 8; j++) {
            const int cb = wn * 64 + j * 8 + 2 * t;
            sX[(rb + g)     * SX_STRIDE + cb]     = fmaxf(acc[i][j][0], 0.f);
            sX[(rb + g)     * SX_STRIDE + cb + 1] = fmaxf(acc[i][j][1], 0.f);
            sX[(rb + 8 + g) * SX_STRIDE + cb]     = fmaxf(acc[i][j][2], 0.f);
            sX[(rb + 8 + g) * SX_STRIDE + cb + 1] = fmaxf(acc[i][j][3], 0.f);
        }
    }
    if (tid < 256) {                 // W3 is [256,2] = 512 floats
        sW[tid]       = W3[tid];
        sW[256 + tid] = W3[256 + tid];
    }
    __syncthreads();

    // ================= Layer 3: out[p, o] = x2[r,:] . W3[:, o] (exact fp32) ===========
    if (tid < 256) {
        const int r = tid >> 1;
        const int o = tid & 1;
        const int p = tile0 + r;
        if (p < P) {
            const float* xr = sX + r * SX_STRIDE;
            float s = 0.f;
#pragma unroll 8
            for (int k = 0; k < 256; k++)
                s = fmaf(xr[k], sW[k * 2 + o], s);
            out[(size_t)p * 2 + o] = s;
        }
    }
}

extern "C" void kernel_launch(void* const* d_in, const int* in_sizes, int n_in,
                              void* d_out, int out_size)
{
    const float* h_nodes = (const float*)d_in[0];
    const int*   dst     = (const int*)  d_in[1];
    const int*   src     = (const int*)  d_in[2];
    const float* W1      = (const float*)d_in[3];
    const float* W2      = (const float*)d_in[4];
    const float* W3      = (const float*)d_in[5];
    float*       out     = (float*)d_out;

    const int P = in_sizes[1];   // number of pairs

    const size_t smem_bytes = (size_t)SMEM_FLOATS * sizeof(float);
    cudaFuncSetAttribute(edge_mlp_kernel,
                         cudaFuncAttributeMaxDynamicSharedMemorySize,
                         (int)smem_bytes);

    const int grid = (P + M_TILE - 1) / M_TILE;
    edge_mlp_kernel<<<grid, THREADS, smem_bytes>>>(h_nodes, dst, src, W1, W2, W3, out, P);
}